// round 10
// baseline (speedup 1.0000x reference)
#include <cuda_runtime.h>

#define BN  16384   // number of segments
#define TPB 256     // phase A block size
#define IT  8       // int4-chunks per lane per warp tile (phase A)

#define TPB_B 128   // phase B block size (4 warps/block)

// Segment start offsets. g_start[s] = first node index of segment s; g_start[BN] = n.
// Fully rewritten on every launch (no reset pass needed). No cudaMalloc.
__device__ int g_start[BN + 1];

__device__ __forceinline__ void fill_range(int u, int v, int i) {
    // batch is sorted: for every s in (u, v], segment s starts at node i.
    int s  = (u + 1 > 0)  ? u + 1 : 0;
    int se = (v < BN)     ? v     : BN;
    for (; s <= se; ++s) g_start[s] = i;
}

// ---------------- phase A: boundary detection over batch (20 MB) ----------------
__global__ void __launch_bounds__(TPB) boundaries_kernel(
    const int4* __restrict__ bat4,
    const int*  __restrict__ batch,
    int n)
{
    const int lane = threadIdx.x & 31;
    const int warp = blockIdx.x * (TPB / 32) + (threadIdx.x >> 5);
    const int nchunks = n >> 2;           // full int4 chunks
    const int c0 = warp * (32 * IT);

    if (c0 < nchunks) {
        int carry = (c0 == 0) ? -1 : batch[c0 * 4 - 1];  // element before this warp tile
        #pragma unroll
        for (int it = 0; it < IT; ++it) {
            int  c   = c0 + it * 32 + lane;
            bool act = (c < nchunks);
            int4 b   = make_int4(0, 0, 0, 0);
            if (act) b = bat4[c];

            int pl   = __shfl_up_sync(0xffffffffu, b.w, 1);
            int prev = (lane == 0) ? carry : pl;

            if (act) {
                if ((prev ^ b.x) | (b.x ^ b.y) | (b.y ^ b.z) | (b.z ^ b.w)) {
                    int i = c * 4;
                    fill_range(prev, b.x, i);
                    fill_range(b.x,  b.y, i + 1);
                    fill_range(b.y,  b.z, i + 2);
                    fill_range(b.z,  b.w, i + 3);
                }
            }
            carry = __shfl_sync(0xffffffffu, b.w, 31);
        }
    }

    // One thread handles the scalar tail (< 4 elems) and the end sentinel.
    if (blockIdx.x == 0 && threadIdx.x == 0) {
        int i0   = nchunks * 4;
        int prev = (i0 == 0) ? -1 : batch[i0 - 1];
        for (int i = i0; i < n; ++i) {
            int b = batch[i];
            fill_range(prev, b, i);
            prev = b;
        }
        fill_range(prev, BN, n);   // g_start[s]=n beyond the last segment, incl. sentinel
    }
}

// -------- phase B: 2 segments per warp, interleaved streams + fused MLP --------
// 2048 blocks * 128 thr, 16 blocks/SM cap -> single wave on 148+ SMs.
__global__ void __launch_bounds__(TPB_B, 16) segmean_mlp_kernel(
    const float4* __restrict__ x,
    const float*  __restrict__ u,
    const float*  __restrict__ W1,  // [5,5] row-major
    const float*  __restrict__ b1,  // [5]
    const float*  __restrict__ W2,  // [5,1]
    const float*  __restrict__ b2,  // [1]
    float* __restrict__ out)
{
    const int warp = blockIdx.x * (TPB_B / 32) + (threadIdx.x >> 5);
    const int lane = threadIdx.x & 31;
    const int seg0 = warp * 2;            // grid covers BN/2 warps exactly

    const int s0 = g_start[seg0];
    const int s1 = g_start[seg0 + 1];
    const int e1 = g_start[seg0 + 2];
    const int n0 = s1 - s0;
    const int n1 = e1 - s1;

    float4 a0 = make_float4(0.f, 0.f, 0.f, 0.f);
    float4 a1 = make_float4(0.f, 0.f, 0.f, 0.f);

    const float4* p0 = x + s0 + lane;
    const float4* p1 = x + s1 + lane;

    const int m0 = n0 >> 5;               // full 32-wide strides, warp-uniform
    const int m1 = n1 >> 5;
    const int mc = (m0 < m1) ? m0 : m1;

    // dual-stream main loop: 2 independent loads in flight, no divergence
    for (int k = 0; k < mc; ++k) {
        float4 v0 = __ldcs(p0);
        float4 v1 = __ldcs(p1);
        a0.x += v0.x; a0.y += v0.y; a0.z += v0.z; a0.w += v0.w;
        a1.x += v1.x; a1.y += v1.y; a1.z += v1.z; a1.w += v1.w;
        p0 += 32; p1 += 32;
    }
    // drain stream 0 (warp-uniform count)
    for (int k = mc; k < m0; ++k) {
        float4 v0 = __ldcs(p0);
        a0.x += v0.x; a0.y += v0.y; a0.z += v0.z; a0.w += v0.w;
        p0 += 32;
    }
    // drain stream 1
    for (int k = mc; k < m1; ++k) {
        float4 v1 = __ldcs(p1);
        a1.x += v1.x; a1.y += v1.y; a1.z += v1.z; a1.w += v1.w;
        p1 += 32;
    }
    // masked partial strides (single divergent load each)
    if (lane < (n0 & 31)) {
        float4 v0 = __ldcs(p0);
        a0.x += v0.x; a0.y += v0.y; a0.z += v0.z; a0.w += v0.w;
    }
    if (lane < (n1 & 31)) {
        float4 v1 = __ldcs(p1);
        a1.x += v1.x; a1.y += v1.y; a1.z += v1.z; a1.w += v1.w;
    }

    // butterfly reductions (all lanes end with totals; two independent chains)
    #pragma unroll
    for (int o = 16; o > 0; o >>= 1) {
        a0.x += __shfl_xor_sync(0xffffffffu, a0.x, o);
        a1.x += __shfl_xor_sync(0xffffffffu, a1.x, o);
        a0.y += __shfl_xor_sync(0xffffffffu, a0.y, o);
        a1.y += __shfl_xor_sync(0xffffffffu, a1.y, o);
        a0.z += __shfl_xor_sync(0xffffffffu, a0.z, o);
        a1.z += __shfl_xor_sync(0xffffffffu, a1.z, o);
        a0.w += __shfl_xor_sync(0xffffffffu, a0.w, o);
        a1.w += __shfl_xor_sync(0xffffffffu, a1.w, o);
    }

    // lanes 0 and 1 run the two MLPs concurrently
    if (lane < 2) {
        float4 tot = (lane == 0) ? a0 : a1;
        float  cnt = (float)((lane == 0) ? n0 : n1);
        int    seg = seg0 + lane;
        float  inv = (cnt > 0.f) ? (1.f / cnt) : 0.f;

        float h[5];
        h[0] = __ldg(&u[seg]);
        h[1] = tot.x * inv; h[2] = tot.y * inv;
        h[3] = tot.z * inv; h[4] = tot.w * inv;

        float o = __ldg(&b2[0]);
        #pragma unroll
        for (int j = 0; j < 5; ++j) {
            float t = __ldg(&b1[j]);
            #pragma unroll
            for (int k = 0; k < 5; ++k) t += h[k] * __ldg(&W1[k * 5 + j]);
            t = (t > 0.f) ? t : 0.1f * t;
            o += t * __ldg(&W2[j]);
        }
        out[seg] = o;
    }
}

extern "C" void kernel_launch(void* const* d_in, const int* in_sizes, int n_in,
                              void* d_out, int out_size) {
    const float* x     = (const float*)d_in[0];
    const int*   batch = (const int*)d_in[1];
    const float* u     = (const float*)d_in[2];
    const float* W1    = (const float*)d_in[3];
    const float* b1    = (const float*)d_in[4];
    const float* W2    = (const float*)d_in[5];
    const float* b2    = (const float*)d_in[6];
    float* out = (float*)d_out;

    int n = in_sizes[1];  // number of nodes

    // phase A: boundary detection
    {
        int nchunks = n >> 2;
        long long nwarps = ((long long)nchunks + (32 * IT) - 1) / (32 * IT);
        int nblocks = (int)((nwarps + (TPB / 32) - 1) / (TPB / 32));
        if (nblocks < 1) nblocks = 1;
        boundaries_kernel<<<nblocks, TPB>>>((const int4*)batch, batch, n);
    }

    // phase B: 2 segments per warp -> BN/2 warps -> 2048 blocks (single wave)
    {
        int nblocks = (BN / 2) / (TPB_B / 32);   // 2048
        segmean_mlp_kernel<<<nblocks, TPB_B>>>((const float4*)x, u, W1, b1, W2, b2, out);
    }
}